// round 15
// baseline (speedup 1.0000x reference)
#include <cuda_runtime.h>
#include <cuda_fp16.h>

#define NBATCH 1024
#define MDIM 64
#define CDIM 4
#define TSTEPS 100
#define WARPS_PER_CTA 4

// 4 warps per CTA, one SIM per WARP (warp w -> n = blockIdx.x*4 + w).
// Warps are fully independent (shfl-based p exchange, per-warp sinv slice,
// __syncwarp only) -> each warp lands on its own SMSP (wid % 4), using all
// 4 schedulers instead of piling every 1-warp CTA onto SMSP 0.
// Lane l owns rows l and l+32. Dot in fp16x2 (HFMA2), p scaled by 1024.
__global__ __launch_bounds__(32 * WARPS_PER_CTA)
void metapop_kernel(const float* __restrict__ R,
                    const float* __restrict__ T,
                    const float* __restrict__ rho0,
                    const float* __restrict__ beta,
                    float* __restrict__ out)
{
    __shared__ float sinv[WARPS_PER_CTA][MDIM];   // setup only, per-warp slice

    const int w = threadIdx.x >> 5;               // warp 0..3 -> SMSP w
    const int l = threadIdx.x & 31;               // lane 0..31
    const int n = blockIdx.x * WARPS_PER_CTA + w; // this warp's sim

    const float* Rn = R + (size_t)n * MDIM * MDIM;

    // ---- sinv: lane l sums columns l and l+32 (coalesced; warp-private) ----
    {
        float sA = 0.0f, sB = 0.0f;
        #pragma unroll 8
        for (int i = 0; i < MDIM; i++) {
            sA += Rn[i * MDIM + l];
            sB += Rn[i * MDIM + l + 32];
        }
        sinv[w][l]      = 1.0f / sA;
        sinv[w][l + 32] = 1.0f / sB;
    }
    __syncwarp();

    // ---- T as 16 scalar registers ----
    float Tm[CDIM * CDIM];
    {
        const float* Tn = T + (size_t)n * CDIM * CDIM;
        #pragma unroll
        for (int k = 0; k < CDIM * CDIM; k++) Tm[k] = Tn[k];
    }

    // ---- per-row invariants ----
    // Rpk[h][k] = half2( R[r,k], R[r,k+32] ), k = 0..31, r = l + 32h.
    // Matches the shuffled word w_k = (p_k, p_{k+32}) elementwise.
    __half2 Rpk[2][MDIM / 2];
    float A_[2], B_[2];
    float r0[2], r1[2], r2[2], r3[2];

    #pragma unroll
    for (int h = 0; h < 2; h++) {
        const int r = l + 32 * h;

        #pragma unroll
        for (int k = 0; k < MDIM / 2; k++)
            Rpk[h][k] = __floats2half2_rn(Rn[r * MDIM + k], Rn[r * MDIM + k + 32]);

        // x_j = Rt[n,r,j]*sinv[j]; Rt[n,r,j] = R[(r&15)*64+j, (n&15)*4+(r>>4), n>>4]
        // p = 1 - prod(1 - c x_j) ~= c*A - c^2*B  (>=c^3 dropped, rel err ~1e-6)
        const int b = (n & 15) * 4 + (r >> 4);
        const int a = n >> 4;
        const int cbase = (r & 15) * 64;
        const size_t off = (size_t)b * MDIM + a;
        float s = 0.0f, ss = 0.0f;
        #pragma unroll
        for (int j = 0; j < MDIM; j++) {
            const float x =
                R[(size_t)(cbase + j) * (MDIM * MDIM) + off] * sinv[w][j];
            s += x;
            ss = fmaf(x, x, ss);
        }
        A_[h] = s;
        B_[h] = 0.5f * (s * s - ss);

        const float4 rr = *(const float4*)(rho0 + ((size_t)n * MDIM + r) * CDIM);
        r0[h] = rr.x; r1[h] = rr.y; r2[h] = rr.z; r3[h] = rr.w;
    }

    const float bet = beta[n];
    const float SCALE   = 1024.0f;   // p stored as p*1024 in fp16 (exact pow2)
    const float UNSCALE = 1.0f / 1024.0f;

    float4* out4 = (float4*)out + (size_t)n * MDIM + l;

    for (int t = 0; t < TSTEPS; t++) {
        // trajectory = pre-update state (coalesced STG.128 x2)
        out4[0]  = make_float4(r0[0], r1[0], r2[0], r3[0]);
        out4[32] = make_float4(r0[1], r1[1], r2[1], r3[1]);
        out4 += (size_t)NBATCH * MDIM;

        // p_r = c*(A - c*B), scaled; lane k's word = (p_k, p_{k+32})
        const float c0 = bet * r1[0];
        const float c1 = bet * r1[1];
        const float p0 = (c0 * fmaf(-c0, B_[0], A_[0])) * SCALE;
        const float p1 = (c1 * fmaf(-c1, B_[1], A_[1])) * SCALE;
        const __half2 myp = __floats2half2_rn(p0, p1);
        const unsigned mypu = *reinterpret_cast<const unsigned*>(&myp);

        // dot per row: 32 broadcast shuffles + 32 HFMA2/row.
        // w_k = (p_k, p_{k+32}) from lane k; implicit warp sync via shfl.
        __half2 ac[2][4];
        #pragma unroll
        for (int h = 0; h < 2; h++)
            #pragma unroll
            for (int j = 0; j < 4; j++) ac[h][j] = __float2half2_rn(0.0f);

        #pragma unroll
        for (int k = 0; k < MDIM / 2; k++) {
            const unsigned wu = __shfl_sync(0xFFFFFFFFu, mypu, k);
            const __half2 wv = *reinterpret_cast<const __half2*>(&wu);
            ac[0][k & 3] = __hfma2(Rpk[0][k], wv, ac[0][k & 3]);
            ac[1][k & 3] = __hfma2(Rpk[1][k], wv, ac[1][k & 3]);
        }

        #pragma unroll
        for (int h = 0; h < 2; h++) {
            const __half2 s01 = __hadd2(ac[h][0], ac[h][1]);
            const __half2 s23 = __hadd2(ac[h][2], ac[h][3]);
            const float2 f01 = __half22float2(s01);
            const float2 f23 = __half22float2(s23);
            const float dot =
                ((f01.x + f01.y) + (f23.x + f23.y)) * UNSCALE;

            const float newinf =
                (1.0f - ((r0[h] + r1[h]) + (r2[h] + r3[h]))) * dot;

            // rho_new = rho @ T + newinf*e0 (scalar 4x4), clip below at 0
            float v0 = newinf, v1 = 0.0f, v2 = 0.0f, v3 = 0.0f;
            v0 = fmaf(r0[h], Tm[0],  v0);
            v1 = fmaf(r0[h], Tm[1],  v1);
            v2 = fmaf(r0[h], Tm[2],  v2);
            v3 = fmaf(r0[h], Tm[3],  v3);
            v0 = fmaf(r1[h], Tm[4],  v0);
            v1 = fmaf(r1[h], Tm[5],  v1);
            v2 = fmaf(r1[h], Tm[6],  v2);
            v3 = fmaf(r1[h], Tm[7],  v3);
            v0 = fmaf(r2[h], Tm[8],  v0);
            v1 = fmaf(r2[h], Tm[9],  v1);
            v2 = fmaf(r2[h], Tm[10], v2);
            v3 = fmaf(r2[h], Tm[11], v3);
            v0 = fmaf(r3[h], Tm[12], v0);
            v1 = fmaf(r3[h], Tm[13], v1);
            v2 = fmaf(r3[h], Tm[14], v2);
            v3 = fmaf(r3[h], Tm[15], v3);
            r0[h] = fmaxf(v0, 0.0f);
            r1[h] = fmaxf(v1, 0.0f);
            r2[h] = fmaxf(v2, 0.0f);
            r3[h] = fmaxf(v3, 0.0f);
        }
    }
}

extern "C" void kernel_launch(void* const* d_in, const int* in_sizes, int n_in,
                              void* d_out, int out_size)
{
    const float* R    = (const float*)d_in[0];   // (1024, 64, 64)
    const float* T    = (const float*)d_in[1];   // (1024, 4, 4)
    const float* rho0 = (const float*)d_in[2];   // (1024, 64, 4)
    const float* beta = (const float*)d_in[3];   // (1024,)
    float* out = (float*)d_out;                  // (100, 1024, 64, 4)

    metapop_kernel<<<NBATCH / WARPS_PER_CTA, 32 * WARPS_PER_CTA>>>(
        R, T, rho0, beta, out);
}

// round 16
// speedup vs baseline: 1.0387x; 1.0387x over previous
#include <cuda_runtime.h>
#include <cuda_fp16.h>

#define NBATCH 1024
#define MDIM 64
#define CDIM 4
#define TSTEPS 100

// One WARP per batch element n (block=32, grid=1024). Lane l owns rows l and
// l+32. p-exchange via register shuffles. SOFTWARE-PIPELINED: p(t+1) is
// produced from the early T-column-1 update BEFORE step t's shfl/dot runs,
// so each iteration starts with its shuffle operand ready — the expensive
// shfl->dot->newinf chain gets a full 2-step window to complete.
__global__ __launch_bounds__(32)
void metapop_kernel(const float* __restrict__ R,
                    const float* __restrict__ T,
                    const float* __restrict__ rho0,
                    const float* __restrict__ beta,
                    float* __restrict__ out)
{
    __shared__ float sinv[MDIM];     // setup only

    const int n = blockIdx.x;
    const int l = threadIdx.x;       // lane 0..31

    const float* Rn = R + (size_t)n * MDIM * MDIM;

    // ---- sinv: lane l sums columns l and l+32 (coalesced) ----
    {
        float sA = 0.0f, sB = 0.0f;
        #pragma unroll 8
        for (int i = 0; i < MDIM; i++) {
            sA += Rn[i * MDIM + l];
            sB += Rn[i * MDIM + l + 32];
        }
        sinv[l]      = 1.0f / sA;
        sinv[l + 32] = 1.0f / sB;
    }
    __syncwarp();

    // ---- T as 16 scalar registers ----
    float Tm[CDIM * CDIM];
    {
        const float* Tn = T + (size_t)n * CDIM * CDIM;
        #pragma unroll
        for (int k = 0; k < CDIM * CDIM; k++) Tm[k] = Tn[k];
    }

    // ---- per-row invariants ----
    // Rpk[h][k] = half2( R[r,k], R[r,k+32] ), k = 0..31, r = l + 32h.
    __half2 Rpk[2][MDIM / 2];
    float A_[2], B_[2];
    float r0[2], r1[2], r2[2], r3[2];

    #pragma unroll
    for (int h = 0; h < 2; h++) {
        const int r = l + 32 * h;

        #pragma unroll
        for (int k = 0; k < MDIM / 2; k++)
            Rpk[h][k] = __floats2half2_rn(Rn[r * MDIM + k], Rn[r * MDIM + k + 32]);

        // x_j = Rt[n,r,j]*sinv[j]; Rt[n,r,j] = R[(r&15)*64+j, (n&15)*4+(r>>4), n>>4]
        // p = 1 - prod(1 - c x_j) ~= c*A - c^2*B  (>=c^3 dropped, rel err ~1e-6)
        const int b = (n & 15) * 4 + (r >> 4);
        const int a = n >> 4;
        const int cbase = (r & 15) * 64;
        const size_t off = (size_t)b * MDIM + a;
        float s = 0.0f, ss = 0.0f;
        #pragma unroll
        for (int j = 0; j < MDIM; j++) {
            const float x =
                R[(size_t)(cbase + j) * (MDIM * MDIM) + off] * sinv[j];
            s += x;
            ss = fmaf(x, x, ss);
        }
        A_[h] = s;
        B_[h] = 0.5f * (s * s - ss);

        const float4 rr = *(const float4*)(rho0 + ((size_t)n * MDIM + r) * CDIM);
        r0[h] = rr.x; r1[h] = rr.y; r2[h] = rr.z; r3[h] = rr.w;
    }

    const float bet = beta[n];
    const float SCALE   = 1024.0f;   // p stored as p*1024 in fp16 (exact pow2)
    const float UNSCALE = 1.0f / 1024.0f;

    // ---- prologue: p(0) from rho(0) ----
    unsigned mypu;
    {
        const float c0 = bet * r1[0];
        const float c1 = bet * r1[1];
        const float p0 = (c0 * fmaf(-c0, B_[0], A_[0])) * SCALE;
        const float p1 = (c1 * fmaf(-c1, B_[1], A_[1])) * SCALE;
        const __half2 myp = __floats2half2_rn(p0, p1);
        mypu = *reinterpret_cast<const unsigned*>(&myp);
    }

    float4* out4 = (float4*)out + (size_t)n * MDIM + l;

    for (int t = 0; t < TSTEPS; t++) {
        // (1) trajectory = pre-update state (coalesced STG.128 x2)
        out4[0]  = make_float4(r0[0], r1[0], r2[0], r3[0]);
        out4[32] = make_float4(r0[1], r1[1], r2[1], r3[1]);
        out4 += (size_t)NBATCH * MDIM;

        // (2) EARLY: compartments 1..3 of rho(t+1) — independent of the dot.
        //     (T columns 1..3; all terms >=0 so clip is identity, kept cheap)
        float r1n[2], r2n[2], r3n[2];
        #pragma unroll
        for (int h = 0; h < 2; h++) {
            float v1 = 0.0f, v2 = 0.0f, v3 = 0.0f;
            v1 = fmaf(r0[h], Tm[1],  v1);
            v2 = fmaf(r0[h], Tm[2],  v2);
            v3 = fmaf(r0[h], Tm[3],  v3);
            v1 = fmaf(r1[h], Tm[5],  v1);
            v2 = fmaf(r1[h], Tm[6],  v2);
            v3 = fmaf(r1[h], Tm[7],  v3);
            v1 = fmaf(r2[h], Tm[9],  v1);
            v2 = fmaf(r2[h], Tm[10], v2);
            v3 = fmaf(r2[h], Tm[11], v3);
            v1 = fmaf(r3[h], Tm[13], v1);
            v2 = fmaf(r3[h], Tm[14], v2);
            v3 = fmaf(r3[h], Tm[15], v3);
            r1n[h] = fmaxf(v1, 0.0f);
            r2n[h] = fmaxf(v2, 0.0f);
            r3n[h] = fmaxf(v3, 0.0f);
        }

        // (3) EARLY: p(t+1) from r1n — ready before step t's dot completes,
        //     so next iteration's shuffles fire at iteration start.
        unsigned mypu_next;
        {
            const float c0 = bet * r1n[0];
            const float c1 = bet * r1n[1];
            const float p0 = (c0 * fmaf(-c0, B_[0], A_[0])) * SCALE;
            const float p1 = (c1 * fmaf(-c1, B_[1], A_[1])) * SCALE;
            const __half2 myp = __floats2half2_rn(p0, p1);
            mypu_next = *reinterpret_cast<const unsigned*>(&myp);
        }

        // (4) dot for step t using p(t) (operand ready since last iteration)
        __half2 ac[2][4];
        #pragma unroll
        for (int h = 0; h < 2; h++)
            #pragma unroll
            for (int j = 0; j < 4; j++) ac[h][j] = __float2half2_rn(0.0f);

        #pragma unroll
        for (int k = 0; k < MDIM / 2; k++) {
            const unsigned wu = __shfl_sync(0xFFFFFFFFu, mypu, k);
            const __half2 wv = *reinterpret_cast<const __half2*>(&wu);
            ac[0][k & 3] = __hfma2(Rpk[0][k], wv, ac[0][k & 3]);
            ac[1][k & 3] = __hfma2(Rpk[1][k], wv, ac[1][k & 3]);
        }

        // (5) newinf -> compartment 0 of rho(t+1)
        #pragma unroll
        for (int h = 0; h < 2; h++) {
            const __half2 s01 = __hadd2(ac[h][0], ac[h][1]);
            const __half2 s23 = __hadd2(ac[h][2], ac[h][3]);
            const float2 f01 = __half22float2(s01);
            const float2 f23 = __half22float2(s23);
            const float dot =
                ((f01.x + f01.y) + (f23.x + f23.y)) * UNSCALE;

            const float newinf =
                (1.0f - ((r0[h] + r1[h]) + (r2[h] + r3[h]))) * dot;

            float v0 = newinf;
            v0 = fmaf(r0[h], Tm[0],  v0);
            v0 = fmaf(r1[h], Tm[4],  v0);
            v0 = fmaf(r2[h], Tm[8],  v0);
            v0 = fmaf(r3[h], Tm[12], v0);
            r0[h] = fmaxf(v0, 0.0f);
            r1[h] = r1n[h];
            r2[h] = r2n[h];
            r3[h] = r3n[h];
        }

        // (6) rotate pipelined p
        mypu = mypu_next;
    }
}

extern "C" void kernel_launch(void* const* d_in, const int* in_sizes, int n_in,
                              void* d_out, int out_size)
{
    const float* R    = (const float*)d_in[0];   // (1024, 64, 64)
    const float* T    = (const float*)d_in[1];   // (1024, 4, 4)
    const float* rho0 = (const float*)d_in[2];   // (1024, 64, 4)
    const float* beta = (const float*)d_in[3];   // (1024,)
    float* out = (float*)d_out;                  // (100, 1024, 64, 4)

    metapop_kernel<<<NBATCH, 32>>>(R, T, rho0, beta, out);
}

// round 17
// speedup vs baseline: 1.0548x; 1.0155x over previous
#include <cuda_runtime.h>
#include <cuda_fp16.h>

#define NBATCH 1024
#define MDIM 64
#define CDIM 4
#define TSTEPS 100

// One WARP per batch element n (block=32, grid=1024). Lane l owns rows l,l+32.
// UNROLL-BY-2: rho_{1..3}(t+1) are linear in rho(t) (newinf only feeds comp 0),
// so p(t) AND p(t+1) are both known from rho(t) -> dot(t) and dot(t+1) run as
// one fully-parallel bundle (64 shfl + 128 HFMA2, independent), then two cheap
// scalar newinf fixups. Halves the serialized dot-phases: 50 instead of 100.
__global__ __launch_bounds__(32)
void metapop_kernel(const float* __restrict__ R,
                    const float* __restrict__ T,
                    const float* __restrict__ rho0,
                    const float* __restrict__ beta,
                    float* __restrict__ out)
{
    __shared__ float sinv[MDIM];     // setup only

    const int n = blockIdx.x;
    const int l = threadIdx.x;       // lane 0..31

    const float* Rn = R + (size_t)n * MDIM * MDIM;

    // ---- sinv: lane l sums columns l and l+32 (coalesced) ----
    {
        float sA = 0.0f, sB = 0.0f;
        #pragma unroll 8
        for (int i = 0; i < MDIM; i++) {
            sA += Rn[i * MDIM + l];
            sB += Rn[i * MDIM + l + 32];
        }
        sinv[l]      = 1.0f / sA;
        sinv[l + 32] = 1.0f / sB;
    }
    __syncwarp();

    // ---- T as 16 scalar registers ----
    float Tm[CDIM * CDIM];
    {
        const float* Tn = T + (size_t)n * CDIM * CDIM;
        #pragma unroll
        for (int k = 0; k < CDIM * CDIM; k++) Tm[k] = Tn[k];
    }

    // ---- per-row invariants ----
    __half2 Rpk[2][MDIM / 2];        // (R[r,k], R[r,k+32]), r = l + 32h
    float A_[2], B_[2];
    float r0[2], r1[2], r2[2], r3[2];

    #pragma unroll
    for (int h = 0; h < 2; h++) {
        const int r = l + 32 * h;

        #pragma unroll
        for (int k = 0; k < MDIM / 2; k++)
            Rpk[h][k] = __floats2half2_rn(Rn[r * MDIM + k], Rn[r * MDIM + k + 32]);

        // x_j = Rt[n,r,j]*sinv[j]; Rt[n,r,j] = R[(r&15)*64+j, (n&15)*4+(r>>4), n>>4]
        // p = 1 - prod(1 - c x_j) ~= c*A - c^2*B
        const int b = (n & 15) * 4 + (r >> 4);
        const int a = n >> 4;
        const int cbase = (r & 15) * 64;
        const size_t off = (size_t)b * MDIM + a;
        float s = 0.0f, ss = 0.0f;
        #pragma unroll
        for (int j = 0; j < MDIM; j++) {
            const float x =
                R[(size_t)(cbase + j) * (MDIM * MDIM) + off] * sinv[j];
            s += x;
            ss = fmaf(x, x, ss);
        }
        A_[h] = s;
        B_[h] = 0.5f * (s * s - ss);

        const float4 rr = *(const float4*)(rho0 + ((size_t)n * MDIM + r) * CDIM);
        r0[h] = rr.x; r1[h] = rr.y; r2[h] = rr.z; r3[h] = rr.w;
    }

    const float bet = beta[n];
    const float SCALE   = 1024.0f;
    const float UNSCALE = 1.0f / 1024.0f;

    float4* out4 = (float4*)out + (size_t)n * MDIM + l;
    const size_t ostride = (size_t)NBATCH * MDIM;

    #pragma unroll 1
    for (int t = 0; t < TSTEPS; t += 2) {
        // store rho(t)
        out4[0]  = make_float4(r0[0], r1[0], r2[0], r3[0]);
        out4[32] = make_float4(r0[1], r1[1], r2[1], r3[1]);
        out4 += ostride;

        // linear T-update sigma = rho(t) @ T (no newinf yet; comps 1..3 final)
        float s0[2], s1[2], s2[2], s3[2];
        #pragma unroll
        for (int h = 0; h < 2; h++) {
            float v0 = r0[h] * Tm[0],  v1 = r0[h] * Tm[1];
            float v2 = r0[h] * Tm[2],  v3 = r0[h] * Tm[3];
            v0 = fmaf(r1[h], Tm[4],  v0); v1 = fmaf(r1[h], Tm[5],  v1);
            v2 = fmaf(r1[h], Tm[6],  v2); v3 = fmaf(r1[h], Tm[7],  v3);
            v0 = fmaf(r2[h], Tm[8],  v0); v1 = fmaf(r2[h], Tm[9],  v1);
            v2 = fmaf(r2[h], Tm[10], v2); v3 = fmaf(r2[h], Tm[11], v3);
            v0 = fmaf(r3[h], Tm[12], v0); v1 = fmaf(r3[h], Tm[13], v1);
            v2 = fmaf(r3[h], Tm[14], v2); v3 = fmaf(r3[h], Tm[15], v3);
            s0[h] = v0;                 // newinf(t) added later, then clipped
            s1[h] = fmaxf(v1, 0.0f);    // final rho1(t+1)
            s2[h] = fmaxf(v2, 0.0f);
            s3[h] = fmaxf(v3, 0.0f);
        }

        // p(t) from rho1(t) and p(t+1) from rho1(t+1) — both known NOW
        unsigned mypuA, mypuB;
        {
            const float cA0 = bet * r1[0], cA1 = bet * r1[1];
            const __half2 pa = __floats2half2_rn(
                (cA0 * fmaf(-cA0, B_[0], A_[0])) * SCALE,
                (cA1 * fmaf(-cA1, B_[1], A_[1])) * SCALE);
            mypuA = *reinterpret_cast<const unsigned*>(&pa);
            const float cB0 = bet * s1[0], cB1 = bet * s1[1];
            const __half2 pb = __floats2half2_rn(
                (cB0 * fmaf(-cB0, B_[0], A_[0])) * SCALE,
                (cB1 * fmaf(-cB1, B_[1], A_[1])) * SCALE);
            mypuB = *reinterpret_cast<const unsigned*>(&pb);
        }

        // both dots as one independent bundle: 64 shfl + 128 HFMA2
        __half2 acA[2][4], acB[2][4];
        #pragma unroll
        for (int h = 0; h < 2; h++)
            #pragma unroll
            for (int j = 0; j < 4; j++) {
                acA[h][j] = __float2half2_rn(0.0f);
                acB[h][j] = __float2half2_rn(0.0f);
            }
        #pragma unroll
        for (int k = 0; k < MDIM / 2; k++) {
            const unsigned wa = __shfl_sync(0xFFFFFFFFu, mypuA, k);
            const unsigned wb = __shfl_sync(0xFFFFFFFFu, mypuB, k);
            const __half2 wva = *reinterpret_cast<const __half2*>(&wa);
            const __half2 wvb = *reinterpret_cast<const __half2*>(&wb);
            acA[0][k & 3] = __hfma2(Rpk[0][k], wva, acA[0][k & 3]);
            acA[1][k & 3] = __hfma2(Rpk[1][k], wva, acA[1][k & 3]);
            acB[0][k & 3] = __hfma2(Rpk[0][k], wvb, acB[0][k & 3]);
            acB[1][k & 3] = __hfma2(Rpk[1][k], wvb, acB[1][k & 3]);
        }

        // finish step t: rho(t+1)
        float q0[2], q1[2], q2[2], q3[2];
        #pragma unroll
        for (int h = 0; h < 2; h++) {
            const __half2 u01 = __hadd2(acA[h][0], acA[h][1]);
            const __half2 u23 = __hadd2(acA[h][2], acA[h][3]);
            const float2 f01 = __half22float2(u01);
            const float2 f23 = __half22float2(u23);
            const float dotA = ((f01.x + f01.y) + (f23.x + f23.y)) * UNSCALE;
            const float newinf =
                (1.0f - ((r0[h] + r1[h]) + (r2[h] + r3[h]))) * dotA;
            q0[h] = fmaxf(s0[h] + newinf, 0.0f);
            q1[h] = s1[h]; q2[h] = s2[h]; q3[h] = s3[h];
        }

        // store rho(t+1)
        out4[0]  = make_float4(q0[0], q1[0], q2[0], q3[0]);
        out4[32] = make_float4(q0[1], q1[1], q2[1], q3[1]);
        out4 += ostride;

        // finish step t+1: rho(t+2) = rho(t+1)@T + newinf(t+1)*e0
        #pragma unroll
        for (int h = 0; h < 2; h++) {
            const __half2 u01 = __hadd2(acB[h][0], acB[h][1]);
            const __half2 u23 = __hadd2(acB[h][2], acB[h][3]);
            const float2 f01 = __half22float2(u01);
            const float2 f23 = __half22float2(u23);
            const float dotB = ((f01.x + f01.y) + (f23.x + f23.y)) * UNSCALE;
            const float newinf =
                (1.0f - ((q0[h] + q1[h]) + (q2[h] + q3[h]))) * dotB;

            float v0 = newinf, v1 = 0.0f, v2 = 0.0f, v3 = 0.0f;
            v0 = fmaf(q0[h], Tm[0],  v0); v1 = fmaf(q0[h], Tm[1],  v1);
            v2 = fmaf(q0[h], Tm[2],  v2); v3 = fmaf(q0[h], Tm[3],  v3);
            v0 = fmaf(q1[h], Tm[4],  v0); v1 = fmaf(q1[h], Tm[5],  v1);
            v2 = fmaf(q1[h], Tm[6],  v2); v3 = fmaf(q1[h], Tm[7],  v3);
            v0 = fmaf(q2[h], Tm[8],  v0); v1 = fmaf(q2[h], Tm[9],  v1);
            v2 = fmaf(q2[h], Tm[10], v2); v3 = fmaf(q2[h], Tm[11], v3);
            v0 = fmaf(q3[h], Tm[12], v0); v1 = fmaf(q3[h], Tm[13], v1);
            v2 = fmaf(q3[h], Tm[14], v2); v3 = fmaf(q3[h], Tm[15], v3);
            r0[h] = fmaxf(v0, 0.0f);
            r1[h] = fmaxf(v1, 0.0f);
            r2[h] = fmaxf(v2, 0.0f);
            r3[h] = fmaxf(v3, 0.0f);
        }
    }
}

extern "C" void kernel_launch(void* const* d_in, const int* in_sizes, int n_in,
                              void* d_out, int out_size)
{
    const float* R    = (const float*)d_in[0];   // (1024, 64, 64)
    const float* T    = (const float*)d_in[1];   // (1024, 4, 4)
    const float* rho0 = (const float*)d_in[2];   // (1024, 64, 4)
    const float* beta = (const float*)d_in[3];   // (1024,)
    float* out = (float*)d_out;                  // (100, 1024, 64, 4)

    metapop_kernel<<<NBATCH, 32>>>(R, T, rho0, beta, out);
}